// round 16
// baseline (speedup 1.0000x reference)
#include <cuda_runtime.h>
#include <math_constants.h>

#define Bn 16
#define Nn 256
#define Rr 24
#define Ll 32
#define CLU 8            // CTAs per batch
#define THR 1024
#define Gg 8             // k-steps per publish
#define NGRP (Nn / Gg)   // 32 groups
#define RING 4           // strip ring depth

// Scratch (device globals; no allocation allowed)
__device__ float g_dist[Bn * Nn * Nn];                          // edge matrix
__device__ __align__(16) float2 g_stage2[RING][Bn][Gg][Gg][32]; // ring, [g][m][l]
__device__ float g_acc[160];                                    // scalar accumulators
__device__ int   g_pub[Bn];                                     // groups published
__device__ int   g_rc[Bn][NGRP];                                // read counters

// Output layout (flattened tuple, float32):
#define OFF_TDT  0
#define OFF_TRT  16
#define OFF_TAT  32
#define OFF_TD   96
#define OFF_UNS  112
#define OFF_TTR  128
#define OFF_TT   144
#define OFF_NDIS (144 + Bn * Nn * Nn)

// ---------------------------------------------------------------------------
__global__ void k_init() {
    int idx = blockIdx.x * blockDim.x + threadIdx.x;   // exactly B*N*N threads
    g_dist[idx] = CUDART_INF_F;
    if (idx < 160) g_acc[idx] = 0.0f;
    if (idx < Bn)  g_pub[idx] = 0;
    if (idx < Bn * NGRP) (&g_rc[0][0])[idx] = 0;
}

// Dummy so fw_exact lands at launch index 3 (ncu capture slot)
__global__ void k_dummy() {}

// ---------------------------------------------------------------------------
// Edge build (unchanged): XLA ReduceWindowRewriter cumsum, base_length = 16.
// ---------------------------------------------------------------------------
__global__ void k_edges(const float* __restrict__ dtm,
                        const int*   __restrict__ routes) {
    int br = blockIdx.x;
    int b = br / Rr;
    int lane = threadIdx.x;

    __shared__ int   ss[Ll];
    __shared__ float lf[Ll], lr[Ll];
    __shared__ float cf[Ll], cr[Ll];

    const int* rt = routes + br * Ll;
    int s = rt[lane];
    ss[lane] = s;
    __syncwarp();

    int snext = ss[(lane + 1 < Ll) ? lane + 1 : Ll - 1];
    float vf = 0.0f, vr = 0.0f;
    if (lane < Ll - 1) {
        vf = __fadd_rn(dtm[(b * Nn + s) * Nn + snext], 60.0f);
        vr = __fadd_rn(dtm[(b * Nn + snext) * Nn + s], 60.0f);
    }
    lf[lane] = vf;
    lr[lane] = vr;
    __syncwarp();

    if (lane == 0) {
        cf[0] = 0.0f; cr[0] = 0.0f;
        float a0f = 0.0f, a1f = 0.0f, Tf = 0.0f;
        float a0r = 0.0f, a1r = 0.0f, Tr = 0.0f;
        float srt = 0.0f;
        #pragma unroll
        for (int m = 0; m < Ll - 1; m++) {
            if (m < 16) {
                a0f = __fadd_rn(a0f, lf[m]);
                a0r = __fadd_rn(a0r, lr[m]);
                cf[m + 1] = a0f;
                cr[m + 1] = a0r;
                if (m == 15) { Tf = a0f; Tr = a0r; }
            } else {
                a1f = __fadd_rn(a1f, lf[m]);
                a1r = __fadd_rn(a1r, lr[m]);
                cf[m + 1] = __fadd_rn(Tf, a1f);
                cr[m + 1] = __fadd_rn(Tr, a1r);
            }
            srt += lf[m] + lr[m];
        }
        atomicAdd(&g_acc[OFF_TRT + b], srt);       // total route time
    }
    __syncwarp();

    unsigned int* eU = reinterpret_cast<unsigned int*>(g_dist);
    for (int p = lane; p < Ll * Ll; p += 32) {
        int i = p >> 5, j = p & 31;
        if (i < j) {
            int si = ss[i], sj = ss[j];
            float tf = __fsub_rn(cf[j], cf[i]);
            atomicMin(&eU[(b * Nn + si) * Nn + sj], __float_as_uint(tf));
            float tr = __fsub_rn(cr[j], cr[i]);
            atomicMin(&eU[(b * Nn + sj) * Nn + si], __float_as_uint(tr));
        }
    }
}

// ---------------------------------------------------------------------------
__device__ __forceinline__ float warp_sum(float v) {
    #pragma unroll
    for (int o = 16; o; o >>= 1) v += __shfl_down_sync(0xffffffffu, v, o);
    return v;
}
__device__ __forceinline__ int ld_acq(const int* p) {
    int v;
    asm volatile("ld.acquire.gpu.b32 %0, [%1];" : "=r"(v) : "l"(p) : "memory");
    return v;
}
__device__ __forceinline__ void st_rel(int* p, int v) {
    asm volatile("st.release.gpu.b32 [%0], %1;" :: "l"(p), "r"(v) : "memory");
}
__device__ __forceinline__ void red_rel_add(int* p, int v) {
    asm volatile("red.release.gpu.global.add.s32 [%0], %1;" :: "l"(p), "r"(v) : "memory");
}
__device__ __forceinline__ int ld_acq_cta(const int* p) {
    int v;
    asm volatile("ld.acquire.cta.b32 %0, [%1];" : "=r"(v) : "l"(p) : "memory");
    return v;
}
__device__ __forceinline__ void st_rel_cta(int* p, int v) {
    asm volatile("st.release.cta.b32 [%0], %1;" :: "l"(p), "r"(v) : "memory");
}
// Packed (d,h) add: one instruction, bit-identical to two __fadd_rn.
__device__ __forceinline__ float2 addx2(float2 a, float2 b) {
    unsigned long long ra = *reinterpret_cast<unsigned long long*>(&a);
    unsigned long long rb = *reinterpret_cast<unsigned long long*>(&b);
    unsigned long long rr;
    asm("add.rn.f32x2 %0, %1, %2;" : "=l"(rr) : "l"(ra), "l"(rb));
    return *reinterpret_cast<float2*>(&rr);
}
#define BAR256() asm volatile("bar.sync 3, 256;" ::: "memory")

__global__ void __launch_bounds__(THR, 1)
fw_exact(const float* __restrict__ demand, float* __restrict__ out) {
    extern __shared__ unsigned char smraw[];
    // sCol: 3 bufs x [g][m][l] of float2 = 49152 B
    float2 (*sCol)[Gg][Gg][32] = reinterpret_cast<float2 (*)[Gg][Gg][32]>(smraw);
    float2 (*sP)[Gg] = reinterpret_cast<float2 (*)[Gg]>(smraw + 49152);
    int* sGD    = reinterpret_cast<int*>(smraw + 49152 + 512);     // [32]
    int* sReady = reinterpret_cast<int*>(smraw + 49152 + 512 + 128);

    int b = blockIdx.x >> 3;
    int c = blockIdx.x & 7;
    int t = threadIdx.x;
    int lane = t & 31;
    int wid = t >> 5;             // warp = local column 0..31
    int jg = c * 32 + wid;        // global column owned by this warp

    if (t < 32) sGD[t] = 0;
    if (t == 0) sReady[0] = -1;
    __syncthreads();

    // Load 8 owned cells (rows 8*lane+m, column jg); diagonal=0; hops derived
    float d[8], h[8];
    #pragma unroll
    for (int m = 0; m < 8; m++) {
        int row = lane * 8 + m;
        float dd = g_dist[b * Nn * Nn + row * Nn + jg];
        if (row == jg) dd = 0.0f;
        d[m] = dd;
        h[m] = (row != jg && dd != CUDART_INF_F) ? 1.0f : 0.0f;
    }

    // Publisher tail: window warps only (warps (p&3)*8 .. +8 of owner CTA).
    // Assumes group-p raw columns already staged into sCol[p%3].
    auto publish = [&](int p) {
        if (c != (p >> 2)) return;
        int jl0w = (p & 3) * Gg;
        if (wid < jl0w || wid >= jl0w + Gg) return;
        int e = t - jl0w * 32;          // 0..255 within window
        int bufN = p % 3;
        if (e == 0 && p >= RING) {
            while (ld_acq(&g_rc[b][p - RING]) < CLU) __nanosleep(64);
        }
        BAR256();                        // staged cols visible; rc ok
        if (wid == jl0w) {               // pivot warp: 8x8 block via shuffles
            int l = lane & 7;
            float2 M[8];
            #pragma unroll
            for (int i = 0; i < 8; i++) M[i] = sCol[bufN][l][i][p];
            #pragma unroll
            for (int g = 0; g < 8; g++) {
                if (lane < 8) sP[g][lane] = M[g];    // snapshot row g
                float2 Mg = M[g];
                #pragma unroll
                for (int i = 0; i < 8; i++) {
                    unsigned long long mi =
                        *reinterpret_cast<unsigned long long*>(&M[i]);
                    unsigned long long cg = __shfl_sync(0xffffffffu, mi, g);
                    float2 cgf = *reinterpret_cast<float2*>(&cg);
                    float2 alt = addx2(cgf, Mg);
                    if (alt.x < M[i].x) M[i] = alt;
                }
            }
        }
        BAR256();                        // sP ready
        {
            int m = e >> 5, l2 = e & 31; // this thread handles row l2*8+m
            float2 cp[8];
            #pragma unroll
            for (int g = 0; g < Gg; g++) cp[g] = sCol[bufN][g][m][l2];
            #pragma unroll
            for (int g = 0; g < Gg - 1; g++) {
                #pragma unroll
                for (int g2 = g + 1; g2 < Gg; g2++) {
                    float2 alt = addx2(cp[g], sP[g][g2]);
                    if (alt.x < cp[g2].x) cp[g2] = alt;
                }
            }
            float2* ring = &g_stage2[p & 3][b][0][0][0];
            #pragma unroll
            for (int g = 0; g < Gg; g++) {
                sCol[bufN][g][m][l2] = cp[g];
                __stcg(reinterpret_cast<double*>(&ring[g * 256 + m * 32 + l2]),
                       *reinterpret_cast<double*>(&cp[g]));
            }
        }
        BAR256();                        // all STS/STG issued
        if (e == 0) {
            st_rel(&g_pub[b], p + 1);    // strips in L2 ring
            st_rel_cta(sReady, p);       // strips in own smem
        }
    };

    // Pre-loop: CTA 0 stages + publishes group 0 (initial columns 0..7)
    if (c == 0 && wid < Gg) {
        #pragma unroll
        for (int m = 0; m < 8; m++)
            sCol[0][wid][m][lane] = make_float2(d[m], h[m]);
    }
    publish(0);

    for (int q = 0; q < NGRP; q++) {
        int buf = q % 3;
        bool mine = (c == (q >> 2));

        if (!mine) {
            if (lane == 0) {
                while (ld_acq(&g_pub[b]) < q + 1) {}
                if (q >= 3) {
                    volatile int* gd = sGD;
                    while (gd[q - 3] < 32) {}    // buf writers vs old readers
                }
            }
            __syncwarp();
            // bulk load: 1024 float4, one per thread (coalesced, linear copy)
            {
                const float4* r4 = reinterpret_cast<const float4*>(
                    &g_stage2[q & 3][b][0][0][0]);
                float4* s4 = reinterpret_cast<float4*>(&sCol[buf][0][0][0]);
                s4[t] = __ldcg(r4 + t);
            }
            __syncthreads();
            if (t == 0) red_rel_add(&g_rc[b][q], 1);
        } else {
            while (ld_acq_cta(sReady) < q) {}    // strips completed in smem
            if (t == 0) red_rel_add(&g_rc[b][q], 1);
        }

        // ---- per-warp: row completion (lane q) then phase C with shfl rows
        int lstar = q;                  // lane holding rows k0..k0+7
        if (lane == lstar) {
            #pragma unroll
            for (int g = 0; g < Gg - 1; g++) {
                float2 dh = make_float2(d[g], h[g]);
                #pragma unroll
                for (int m = g + 1; m < Gg; m++) {
                    float2 alt = addx2(sCol[buf][g][m][lstar], dh);
                    if (alt.x < d[m]) { d[m] = alt.x; h[m] = alt.y; }
                }
            }
        }
        __syncwarp();
        #pragma unroll
        for (int g = 0; g < Gg; g++) {
            float2 me = make_float2(d[g], h[g]);
            unsigned long long rv = __shfl_sync(
                0xffffffffu, *reinterpret_cast<unsigned long long*>(&me), lstar);
            float2 rw = *reinterpret_cast<float2*>(&rv);
            #pragma unroll
            for (int m = 0; m < 8; m++) {
                float2 alt = addx2(sCol[buf][g][m][lane], rw);
                if (alt.x < d[m]) { d[m] = alt.x; h[m] = alt.y; }
            }
        }
        if (lane == 0) atomicAdd(&sGD[q], 1);   // this warp done reading buf

        // ---- stage + publish next group (owner of q+1's window warps only)
        if (q < NGRP - 1 && c == ((q + 1) >> 2)) {
            int p = q + 1;
            int jl0w = (p & 3) * Gg;
            if (wid >= jl0w && wid < jl0w + Gg) {
                if (lane == 0 && p >= 3) {
                    volatile int* gd = sGD;
                    while (gd[p - 3] < 32) {}    // buf p%3 old readers done
                }
                __syncwarp();
                int g = wid - jl0w;
                int bufN = p % 3;
                #pragma unroll
                for (int m = 0; m < 8; m++)
                    sCol[bufN][g][m][lane] = make_float2(d[m], h[m]);
            }
            publish(p);
        }
    }

    // ---- fused epilogue: trip_times + reductions ----
    float a_dt = 0, a_tr = 0, a_un = 0, a_td = 0, a_nd = 0;
    float a_b0 = 0, a_b1 = 0, a_b2 = 0, a_du = 0;

    #pragma unroll
    for (int m = 0; m < 8; m++) {
        int gi = b * Nn * Nn + (lane * 8 + m) * Nn + jg;
        float dd = d[m];
        float hh = h[m];
        float dem = demand[gi];
        bool np = (dd == CUDART_INF_F);
        float pl = np ? 0.0f : __fadd_rn(hh, 1.0f);
        float tr = (pl == 0.0f) ? 0.0f : __fsub_rn(pl, 2.0f);
        float tt = np ? 0.0f : __fadd_rn(dd, __fmul_rn(tr, 300.0f));
        out[OFF_TT + gi] = tt;
        a_dt += dem * tt;
        a_tr += dem * tr;
        a_td += dem;
        if (np) { a_un += dem; if (dem > 0.0f) a_nd += 1.0f; }
        if (tr == 0.0f)      a_b0 += dem;
        else if (tr == 1.0f) a_b1 += dem;
        else if (tr == 2.0f) a_b2 += dem;
        else if (tr > 2.0f)  a_du += dem;
    }

    a_dt = warp_sum(a_dt); a_tr = warp_sum(a_tr); a_un = warp_sum(a_un);
    a_td = warp_sum(a_td); a_nd = warp_sum(a_nd); a_b0 = warp_sum(a_b0);
    a_b1 = warp_sum(a_b1); a_b2 = warp_sum(a_b2); a_du = warp_sum(a_du);

    if (lane == 0) {
        atomicAdd(&g_acc[OFF_TDT + b], a_dt);
        atomicAdd(&g_acc[OFF_TTR + b], a_tr);
        atomicAdd(&g_acc[OFF_UNS + b], a_un);
        atomicAdd(&g_acc[OFF_TD  + b], a_td);
        atomicAdd(&g_acc[144 + b],     a_nd);
        atomicAdd(&g_acc[OFF_TAT + b * 4 + 0], a_b0);
        atomicAdd(&g_acc[OFF_TAT + b * 4 + 1], a_b1);
        atomicAdd(&g_acc[OFF_TAT + b * 4 + 2], a_b2);
        atomicAdd(&g_acc[OFF_TAT + b * 4 + 3], a_du + a_un);
    }
}

// ---------------------------------------------------------------------------
__global__ void k_final(float* out) {
    int t = threadIdx.x;        // 160 threads
    if (t < 144)      out[t] = g_acc[t];
    else if (t < 160) out[OFF_NDIS + (t - 144)] = g_acc[t];
}

// ---------------------------------------------------------------------------
extern "C" void kernel_launch(void* const* d_in, const int* in_sizes, int n_in,
                              void* d_out, int out_size) {
    const float* dtm    = (const float*)d_in[0];
    const float* demand = (const float*)d_in[1];
    const int*   routes = (const int*)d_in[2];
    float* out = (float*)d_out;

    const int SMEM_FW = 49152 + 512 + 128 + 16;
    cudaFuncSetAttribute(fw_exact, cudaFuncAttributeMaxDynamicSharedMemorySize,
                         SMEM_FW);

    k_init<<<(Bn * Nn * Nn) / 256, 256>>>();          // launch 0
    k_edges<<<Bn * Rr, 32>>>(dtm, routes);            // launch 1
    k_dummy<<<1, 32>>>();                             // launch 2 (ncu slot)
    fw_exact<<<Bn * CLU, THR, SMEM_FW>>>(demand, out);// launch 3 (ncu captures)
    k_final<<<1, 160>>>(out);                         // launch 4
}

// round 17
// speedup vs baseline: 1.2879x; 1.2879x over previous
#include <cuda_runtime.h>
#include <math_constants.h>

#define Bn 16
#define Nn 256
#define Rr 24
#define Ll 32
#define CLU 8            // CTAs per batch
#define THR 1024
#define Gg 8             // k-steps per publish
#define NGRP (Nn / Gg)   // 32 groups
#define RING 4           // strip ring depth

// Scratch (device globals; no allocation allowed)
__device__ float g_dist[Bn * Nn * Nn];                      // edge matrix
__device__ __align__(16) float2 g_stage2[RING][Bn][Gg][Nn]; // (d,h) strip ring
__device__ float g_acc[160];                                // scalar accumulators
__device__ int   g_pub[Bn];                                 // groups published
__device__ int   g_rc[Bn][NGRP];                            // per-group read counters

// Output layout (flattened tuple, float32):
#define OFF_TDT  0
#define OFF_TRT  16
#define OFF_TAT  32
#define OFF_TD   96
#define OFF_UNS  112
#define OFF_TTR  128
#define OFF_TT   144
#define OFF_NDIS (144 + Bn * Nn * Nn)

// ---------------------------------------------------------------------------
__global__ void k_init() {
    int idx = blockIdx.x * blockDim.x + threadIdx.x;   // exactly B*N*N threads
    g_dist[idx] = CUDART_INF_F;
    if (idx < 160) g_acc[idx] = 0.0f;
    if (idx < Bn)  g_pub[idx] = 0;
    if (idx < Bn * NGRP) (&g_rc[0][0])[idx] = 0;
}

// Dummy so fw_exact lands at launch index 3 (ncu capture slot)
__global__ void k_dummy() {}

// ---------------------------------------------------------------------------
// Edge build: one warp per (batch, route).
// Cumsum: XLA ReduceWindowRewriter blocked association, base_length = 16.
// ---------------------------------------------------------------------------
__global__ void k_edges(const float* __restrict__ dtm,
                        const int*   __restrict__ routes) {
    int br = blockIdx.x;
    int b = br / Rr;
    int lane = threadIdx.x;

    __shared__ int   ss[Ll];
    __shared__ float lf[Ll], lr[Ll];
    __shared__ float cf[Ll], cr[Ll];

    const int* rt = routes + br * Ll;
    int s = rt[lane];
    ss[lane] = s;
    __syncwarp();

    int snext = ss[(lane + 1 < Ll) ? lane + 1 : Ll - 1];
    float vf = 0.0f, vr = 0.0f;
    if (lane < Ll - 1) {
        vf = __fadd_rn(dtm[(b * Nn + s) * Nn + snext], 60.0f);
        vr = __fadd_rn(dtm[(b * Nn + snext) * Nn + s], 60.0f);
    }
    lf[lane] = vf;
    lr[lane] = vr;
    __syncwarp();

    if (lane == 0) {
        cf[0] = 0.0f; cr[0] = 0.0f;
        float a0f = 0.0f, a1f = 0.0f, Tf = 0.0f;
        float a0r = 0.0f, a1r = 0.0f, Tr = 0.0f;
        float srt = 0.0f;
        #pragma unroll
        for (int m = 0; m < Ll - 1; m++) {
            if (m < 16) {
                a0f = __fadd_rn(a0f, lf[m]);
                a0r = __fadd_rn(a0r, lr[m]);
                cf[m + 1] = a0f;
                cr[m + 1] = a0r;
                if (m == 15) { Tf = a0f; Tr = a0r; }
            } else {
                a1f = __fadd_rn(a1f, lf[m]);
                a1r = __fadd_rn(a1r, lr[m]);
                cf[m + 1] = __fadd_rn(Tf, a1f);
                cr[m + 1] = __fadd_rn(Tr, a1r);
            }
            srt += lf[m] + lr[m];
        }
        atomicAdd(&g_acc[OFF_TRT + b], srt);       // total route time
    }
    __syncwarp();

    unsigned int* eU = reinterpret_cast<unsigned int*>(g_dist);
    for (int p = lane; p < Ll * Ll; p += 32) {
        int i = p >> 5, j = p & 31;
        if (i < j) {
            int si = ss[i], sj = ss[j];
            float tf = __fsub_rn(cf[j], cf[i]);
            atomicMin(&eU[(b * Nn + si) * Nn + sj], __float_as_uint(tf));
            float tr = __fsub_rn(cr[j], cr[i]);
            atomicMin(&eU[(b * Nn + sj) * Nn + si], __float_as_uint(tr));
        }
    }
}

// ---------------------------------------------------------------------------
__device__ __forceinline__ float warp_sum(float v) {
    #pragma unroll
    for (int o = 16; o; o >>= 1) v += __shfl_down_sync(0xffffffffu, v, o);
    return v;
}

__device__ __forceinline__ int ld_acq(const int* p) {
    int v;
    asm volatile("ld.acquire.gpu.b32 %0, [%1];" : "=r"(v) : "l"(p) : "memory");
    return v;
}
__device__ __forceinline__ void st_rel(int* p, int v) {
    asm volatile("st.release.gpu.b32 [%0], %1;" :: "l"(p), "r"(v) : "memory");
}
__device__ __forceinline__ void red_rel_add(int* p, int v) {
    asm volatile("red.release.gpu.global.add.s32 [%0], %1;" :: "l"(p), "r"(v) : "memory");
}
// Packed (d,h) add: one instruction, bit-identical to two __fadd_rn.
__device__ __forceinline__ float2 addx2(float2 a, float2 b) {
    unsigned long long ra = *reinterpret_cast<unsigned long long*>(&a);
    unsigned long long rb = *reinterpret_cast<unsigned long long*>(&b);
    unsigned long long rr;
    asm("add.rn.f32x2 %0, %1, %2;" : "=l"(rr) : "l"(ra), "l"(rb));
    return *reinterpret_cast<float2*>(&rr);
}
#define BAR256() asm volatile("bar.sync 3, 256;" ::: "memory")

__global__ void __launch_bounds__(THR, 1)
fw_exact(const float* __restrict__ demand, float* __restrict__ out) {
    int b = blockIdx.x >> 3;
    int c = blockIdx.x & 7;
    int t = threadIdx.x;
    int j = t & 31;            // local column 0..31
    int rb = t >> 5;           // row block (= warp id) 0..31
    int r0 = rb << 3;          // first of 8 owned rows
    int jg = c * 32 + j;       // global column

    __shared__ __align__(16) float2 sCol[2][Gg][Nn];   // (d,h) strips, double buffer
    __shared__ __align__(16) float2 sRow[Gg][32];
    __shared__ __align__(16) float2 sPiv[Gg][Gg];      // consumer pivot block
    __shared__ float2 sP[Gg][Gg];                      // publisher row-g snapshots

    // Load 8 owned cells; diagonal=0; hops in registers
    float d[8], h[8];
    int base = b * Nn * Nn + r0 * Nn + jg;
    #pragma unroll
    for (int m = 0; m < 8; m++) {
        float dd = g_dist[base + m * Nn];
        if (r0 + m == jg) dd = 0.0f;
        d[m] = dd;
        h[m] = (r0 + m != jg && dd != CUDART_INF_F) ? 1.0f : 0.0f;
    }

    // Pivot evolution for group p, run by warp rb == p of the owner CTA using
    // its own registers (the 64 pivot cells live in threads j in the window).
    // Same rounds/snapshots as the old warp-0 smem version (diag-0 invariance
    // + strict < make in-round read order immaterial) -> bitwise identical.
    auto pivot_evolve = [&](int p) {
        int jl0 = (p & 3) * Gg;
        int src = jl0 + (j & 7);          // mirror: lane holds column j&7
        float2 M[8];
        #pragma unroll
        for (int i = 0; i < 8; i++) {
            float2 me = make_float2(d[i], h[i]);
            unsigned long long v = __shfl_sync(0xffffffffu,
                *reinterpret_cast<unsigned long long*>(&me), src);
            M[i] = *reinterpret_cast<float2*>(&v);
        }
        #pragma unroll
        for (int g = 0; g < 8; g++) {
            if (j < 8) sP[g][j] = M[g];   // snapshot row g (pre-round)
            float2 Mg = M[g];
            #pragma unroll
            for (int i = 0; i < 8; i++) {
                unsigned long long mi =
                    *reinterpret_cast<unsigned long long*>(&M[i]);
                unsigned long long cg = __shfl_sync(0xffffffffu, mi, g);
                float2 cgf = *reinterpret_cast<float2*>(&cg);
                float2 alt = addx2(cgf, Mg);
                if (alt.x < M[i].x) M[i] = alt;
            }
        }
    };

    // Publisher: owner CTA column-completes strips for group p in its smem
    // buffer (p&1) and stores them to the L2 ring. sP was precomputed by warp
    // p before this call; staged columns are in sCol (inline or here).
    auto publish = [&](int p, bool preStaged) {
        if (c == (p >> 2)) {
            if (t == 0 && p >= RING) {
                while (ld_acq(&g_rc[b][p - RING]) < CLU) __nanosleep(64);
            }
            __syncthreads();   // staged cols + sP visible; prior reads done
            int buf = p & 1;
            if (!preStaged) {
                int jl0 = (p & 3) * Gg;
                if (j >= jl0 && j < jl0 + Gg) {
                    int g = j - jl0;
                    #pragma unroll
                    for (int m = 0; m < 8; m++)
                        sCol[buf][g][r0 + m] = make_float2(d[m], h[m]);
                }
                __syncthreads();
            }
            if (t < 256) {
                float2 cp[8];
                #pragma unroll
                for (int g = 0; g < Gg; g++) cp[g] = sCol[buf][g][t];
                #pragma unroll
                for (int g = 0; g < Gg - 1; g++) {
                    #pragma unroll
                    for (int g2 = g + 1; g2 < Gg; g2++) {
                        float2 alt = addx2(cp[g], sP[g][g2]);
                        if (alt.x < cp[g2].x) cp[g2] = alt;
                    }
                }
                #pragma unroll
                for (int g = 0; g < Gg; g++) {
                    sCol[buf][g][t] = cp[g];
                    __stcg(reinterpret_cast<double*>(&g_stage2[p & 3][b][g][t]),
                           *reinterpret_cast<double*>(&cp[g]));
                }
                BAR256();                     // STGs issued
                if (t == 0) st_rel(&g_pub[b], p + 1);
            }
        }
    };

    // Pre-loop: CTA 0 publishes group 0 (initial-state columns 0..7)
    if (c == 0 && rb == 0) pivot_evolve(0);
    publish(0, false);

    for (int q = 0; q < NGRP; q++) {
        int k0 = q * Gg;
        int buf = q & 1;
        bool mine = (c == (q >> 2));   // this CTA published group q

        if (!mine) {
            if (j == 0) {
                while (ld_acq(&g_pub[b]) < q + 1) {}   // busy-poll
            }
            __syncwarp();
            const float2* r2 = &g_stage2[q & 3][b][0][0];
            if (rb == (k0 >> 3)) {
                // pivot block FIRST (prefetch): lane j loads 1 float4
                {
                    int g = j >> 2, m0 = (j & 3) << 1;
                    float4 v = __ldcg(reinterpret_cast<const float4*>(&r2[g * Nn + k0 + m0]));
                    *reinterpret_cast<float4*>(&sPiv[g][m0]) = v;
                }
                // bulk share
                {
                    int pi = t << 1;
                    int g = pi >> 8, i = pi & 255;
                    float4 v = __ldcg(reinterpret_cast<const float4*>(&r2[g * Nn + i]));
                    *reinterpret_cast<float4*>(&sCol[buf][g][i]) = v;
                }
                __syncwarp();
                #pragma unroll
                for (int g = 0; g < Gg - 1; g++) {
                    float2 dh = make_float2(d[g], h[g]);
                    #pragma unroll
                    for (int m = g + 1; m < Gg; m++) {
                        float2 alt = addx2(sPiv[g][m], dh);
                        if (alt.x < d[m]) { d[m] = alt.x; h[m] = alt.y; }
                    }
                }
                #pragma unroll
                for (int m = 0; m < Gg; m++) sRow[m][j] = make_float2(d[m], h[m]);
            } else {
                int pi = t << 1;
                int g = pi >> 8, i = pi & 255;
                float4 v = __ldcg(reinterpret_cast<const float4*>(&r2[g * Nn + i]));
                *reinterpret_cast<float4*>(&sCol[buf][g][i]) = v;
            }
            __syncthreads();
        } else {
            __syncthreads();   // completed strips (publish warps 0-7) visible
            if (rb == (k0 >> 3)) {
                #pragma unroll
                for (int g = 0; g < Gg - 1; g++) {
                    float2 dh = make_float2(d[g], h[g]);
                    #pragma unroll
                    for (int m = g + 1; m < Gg; m++) {
                        float2 alt = addx2(sCol[buf][g][k0 + m], dh);
                        if (alt.x < d[m]) { d[m] = alt.x; h[m] = alt.y; }
                    }
                }
                #pragma unroll
                for (int m = 0; m < Gg; m++) sRow[m][j] = make_float2(d[m], h[m]);
            }
            __syncthreads();
        }
        if (t == 0) red_rel_add(&g_rc[b][q], 1);   // slot q consumed

        // ---- main relax: 8 steps, straight-line, packed (d,h)
        #pragma unroll
        for (int g = 0; g < Gg; g++) {
            const float4* c4 = reinterpret_cast<const float4*>(&sCol[buf][g][r0]);
            float4 q0 = c4[0], q1 = c4[1], q2 = c4[2], q3 = c4[3];
            float2 rw = sRow[g][j];
            float2 cp[8] = { make_float2(q0.x, q0.y), make_float2(q0.z, q0.w),
                             make_float2(q1.x, q1.y), make_float2(q1.z, q1.w),
                             make_float2(q2.x, q2.y), make_float2(q2.z, q2.w),
                             make_float2(q3.x, q3.y), make_float2(q3.z, q3.w) };
            #pragma unroll
            for (int m = 0; m < 8; m++) {
                float2 alt = addx2(cp[m], rw);
                if (alt.x < d[m]) { d[m] = alt.x; h[m] = alt.y; }
            }
        }

        // ---- pivot evolve + inline stage for next group's publish (owner)
        if (q < NGRP - 1) {
            int p = q + 1;
            if (c == (p >> 2)) {
                if (rb == (p & 31)) pivot_evolve(p);
                int jl0 = (p & 3) * Gg;
                if (j >= jl0 && j < jl0 + Gg) {
                    int g = j - jl0;
                    int bufN = p & 1;
                    #pragma unroll
                    for (int m = 0; m < 8; m++)
                        sCol[bufN][g][r0 + m] = make_float2(d[m], h[m]);
                }
            }
            publish(p, true);
        }
    }

    // ---- fused epilogue: trip_times + reductions ----
    float a_dt = 0, a_tr = 0, a_un = 0, a_td = 0, a_nd = 0;
    float a_b0 = 0, a_b1 = 0, a_b2 = 0, a_du = 0;

    #pragma unroll
    for (int m = 0; m < 8; m++) {
        int gi = base + m * Nn;
        float dd = d[m];
        float hh = h[m];
        float dem = demand[gi];
        bool np = (dd == CUDART_INF_F);
        float pl = np ? 0.0f : __fadd_rn(hh, 1.0f);
        float tr = (pl == 0.0f) ? 0.0f : __fsub_rn(pl, 2.0f);
        float tt = np ? 0.0f : __fadd_rn(dd, __fmul_rn(tr, 300.0f));
        out[OFF_TT + gi] = tt;
        a_dt += dem * tt;
        a_tr += dem * tr;
        a_td += dem;
        if (np) { a_un += dem; if (dem > 0.0f) a_nd += 1.0f; }
        if (tr == 0.0f)      a_b0 += dem;
        else if (tr == 1.0f) a_b1 += dem;
        else if (tr == 2.0f) a_b2 += dem;
        else if (tr > 2.0f)  a_du += dem;
    }

    a_dt = warp_sum(a_dt); a_tr = warp_sum(a_tr); a_un = warp_sum(a_un);
    a_td = warp_sum(a_td); a_nd = warp_sum(a_nd); a_b0 = warp_sum(a_b0);
    a_b1 = warp_sum(a_b1); a_b2 = warp_sum(a_b2); a_du = warp_sum(a_du);

    if (j == 0) {   // lane 0 of each warp
        atomicAdd(&g_acc[OFF_TDT + b], a_dt);
        atomicAdd(&g_acc[OFF_TTR + b], a_tr);
        atomicAdd(&g_acc[OFF_UNS + b], a_un);
        atomicAdd(&g_acc[OFF_TD  + b], a_td);
        atomicAdd(&g_acc[144 + b],     a_nd);
        atomicAdd(&g_acc[OFF_TAT + b * 4 + 0], a_b0);
        atomicAdd(&g_acc[OFF_TAT + b * 4 + 1], a_b1);
        atomicAdd(&g_acc[OFF_TAT + b * 4 + 2], a_b2);
        atomicAdd(&g_acc[OFF_TAT + b * 4 + 3], a_du + a_un);
    }
}

// ---------------------------------------------------------------------------
__global__ void k_final(float* out) {
    int t = threadIdx.x;        // 160 threads
    if (t < 144)      out[t] = g_acc[t];
    else if (t < 160) out[OFF_NDIS + (t - 144)] = g_acc[t];
}

// ---------------------------------------------------------------------------
extern "C" void kernel_launch(void* const* d_in, const int* in_sizes, int n_in,
                              void* d_out, int out_size) {
    const float* dtm    = (const float*)d_in[0];
    const float* demand = (const float*)d_in[1];
    const int*   routes = (const int*)d_in[2];
    float* out = (float*)d_out;

    k_init<<<(Bn * Nn * Nn) / 256, 256>>>();        // launch 0
    k_edges<<<Bn * Rr, 32>>>(dtm, routes);          // launch 1
    k_dummy<<<1, 32>>>();                           // launch 2 (ncu slot filler)
    fw_exact<<<Bn * CLU, THR>>>(demand, out);       // launch 3 (ncu captures this)
    k_final<<<1, 160>>>(out);                       // launch 4
}